// round 3
// baseline (speedup 1.0000x reference)
#include <cuda_runtime.h>

#define NCLS   2048
#define NROWS  32768
#define BLOCK  256
#define GRID   (NROWS / BLOCK)   // 128

__device__ float        g_sum   = 0.0f;
__device__ unsigned int g_count = 0u;

__global__ __launch_bounds__(BLOCK) void mpl_fused(const float* __restrict__ x,
                                                   const int* __restrict__ tgt,
                                                   float* __restrict__ out) {
    __shared__ float s_warp[BLOCK / 32];

    const int tid  = threadIdx.x;
    const int lane = tid & 31;
    const int wid  = tid >> 5;
    const int row  = blockIdx.x * BLOCK + tid;

    // Issue independent loads immediately: tgt and x0 don't depend on each other.
    const int   t  = __ldg(&tgt[row]);
    const float x0 = __ldg(&x[(size_t)row * NCLS]);

    float local;
    if (t != 0) {
        // positive set = {1..C-1}; loss collapses to 2-class logistic:
        // loss = log(exp(x0) + exp(xt)) - xt
        const float xt = __ldg(&x[(size_t)row * NCLS + t]);
        local = __logf(__expf(x0) + __expf(xt)) - xt;
    } else {
        local = 0.0f;
    }

    // Rare path (t==0, ~1/2048 rows): full-row logsumexp, handled by the
    // OWNING WARP only — no block-wide sync, no shared queue.
    unsigned zmask = __ballot_sync(0xFFFFFFFFu, t == 0);
    while (zmask) {
        const int src = __ffs(zmask) - 1;
        zmask &= zmask - 1;
        const int zrow = __shfl_sync(0xFFFFFFFFu, row, src);
        const float4* rp = reinterpret_cast<const float4*>(x + (size_t)zrow * NCLS);
        float s = 0.0f;
        #pragma unroll
        for (int j = lane; j < NCLS / 4; j += 32) {
            const float4 v = __ldg(&rp[j]);
            s += __expf(v.x) + __expf(v.y) + __expf(v.z) + __expf(v.w);
        }
        #pragma unroll
        for (int off = 16; off > 0; off >>= 1)
            s += __shfl_down_sync(0xFFFFFFFFu, s, off);
        s = __shfl_sync(0xFFFFFFFFu, s, 0);
        if (lane == src)
            local = __logf(s) - x0;   // neg_sum + exp(x_t), t=0 => full row sum
    }

    // Warp reduce
    float r = local;
    #pragma unroll
    for (int off = 16; off > 0; off >>= 1)
        r += __shfl_down_sync(0xFFFFFFFFu, r, off);
    if (lane == 0) s_warp[wid] = r;
    __syncthreads();

    // Block reduce + grid-level last-block finalize (single launch)
    if (tid == 0) {
        float bs = 0.0f;
        #pragma unroll
        for (int w = 0; w < BLOCK / 32; w++) bs += s_warp[w];
        atomicAdd(&g_sum, bs);                    // RED.ADD.F32 (no return)
        __threadfence();
        const unsigned int arrived = atomicAdd(&g_count, 1u);
        if (arrived == GRID - 1) {
            const float total = atomicAdd(&g_sum, 0.0f);   // coherent read
            out[0] = total / (float)NROWS;
            // reset device state so every graph replay starts identically
            g_sum = 0.0f;
            __threadfence();
            g_count = 0u;
        }
    }
}

extern "C" void kernel_launch(void* const* d_in, const int* in_sizes, int n_in,
                              void* d_out, int out_size) {
    const float* x   = (const float*)d_in[0];
    const int*   tgt = (const int*)d_in[1];
    float*       out = (float*)d_out;

    mpl_fused<<<GRID, BLOCK>>>(x, tgt, out);
}